// round 2
// baseline (speedup 1.0000x reference)
#include <cuda_runtime.h>

// NbitTreeDecoder, two-phase:
//  Phase 1: one thread per level-8 node walks levels 0..7 (shared prefix) and
//           expands its level-8 flag into four 30-bit leaf prefixes (int4 store).
//  Phase 2: one thread per level-9 node reads its prefix + flag and emits the
//           4 leaves (bit-reversal + 3x10-bit field split + scale/offset).

#define N8 65536      // 4^8 level-8 nodes
#define N9 262144     // 4^9 level-9 nodes

__device__ unsigned g_prefix9[N9];   // 27-bit prefix (levels 0..8) per level-9 node

static __device__ __forceinline__ unsigned nth_set_bit(unsigned f, unsigned d) {
    unsigned g = f;
    g = (d > 0u) ? (g & (g - 1u)) : g;
    g = (d > 1u) ? (g & (g - 1u)) : g;
    g = (d > 2u) ? (g & (g - 1u)) : g;
    return (unsigned)__ffs(g) - 1u;
}

__global__ void __launch_bounds__(256)
prefix_kernel(const int* __restrict__ flags) {
    const unsigned n8 = blockIdx.x * blockDim.x + threadIdx.x;  // [0, 4^8)

    // (4^t - 1)/3 offsets for levels 0..8
    const unsigned OFF[9] = {0u, 1u, 5u, 21u, 85u, 341u, 1365u, 5461u, 21845u};

    // Levels 0..7: ancestor node of leaf at level t (t<=7) is n8 >> (16-2t),
    // branch digit is (n8 >> (14-2t)) & 3.
    unsigned prefix = 0u;
#pragma unroll
    for (int t = 0; t < 8; t++) {
        const unsigned nt   = n8 >> (16 - 2 * t);
        const unsigned flag = (unsigned)__ldg(flags + OFF[t] + nt);
        const unsigned d    = (n8 >> (14 - 2 * t)) & 3u;
        prefix = (prefix << 3) | nth_set_bit(flag, d);
    }

    // Level 8: this node's flag; its 4 set bits (ascending) are the nibbles
    // for children d = 0..3.
    unsigned f = (unsigned)__ldg(flags + OFF[8] + n8);
    const unsigned p3 = prefix << 3;
    int4 res;
    res.x = (int)(p3 | ((unsigned)__ffs(f) - 1u));  f &= f - 1u;
    res.y = (int)(p3 | ((unsigned)__ffs(f) - 1u));  f &= f - 1u;
    res.z = (int)(p3 | ((unsigned)__ffs(f) - 1u));  f &= f - 1u;
    res.w = (int)(p3 | ((unsigned)__ffs(f) - 1u));

    reinterpret_cast<int4*>(g_prefix9)[n8] = res;
}

__global__ void __launch_bounds__(256)
leaf_kernel(const int* __restrict__ flags,
            const float* __restrict__ offset,
            const float* __restrict__ scale,
            float* __restrict__ out) {
    const unsigned n9 = blockIdx.x * blockDim.x + threadIdx.x;  // [0, 4^9)

    const unsigned prefix = g_prefix9[n9];                      // 27-bit prefix
    unsigned f = (unsigned)__ldg(flags + 87381u + n9);          // level-9 flag

    const float s0 = scale[0],  s1 = scale[1],  s2 = scale[2];
    const float o0 = offset[0], o1 = offset[1], o2 = offset[2];

    const unsigned p3 = prefix << 3;

    float vals[12];
#pragma unroll
    for (int r = 0; r < 4; r++) {
        const unsigned j  = (unsigned)__ffs(f) - 1u;
        f &= f - 1u;
        const unsigned Xr = __brev(p3 | j) >> 2;                // 30-bit reversal
        vals[3 * r + 0] = fmaf((float)(Xr & 1023u),         s0, o0);
        vals[3 * r + 1] = fmaf((float)((Xr >> 10) & 1023u), s1, o1);
        vals[3 * r + 2] = fmaf((float)(Xr >> 20),           s2, o2);
    }

    float4* outv = reinterpret_cast<float4*>(out + (size_t)n9 * 12u);
    outv[0] = make_float4(vals[0], vals[1],  vals[2],  vals[3]);
    outv[1] = make_float4(vals[4], vals[5],  vals[6],  vals[7]);
    outv[2] = make_float4(vals[8], vals[9],  vals[10], vals[11]);
}

extern "C" void kernel_launch(void* const* d_in, const int* in_sizes, int n_in,
                              void* d_out, int out_size) {
    const int*   flags  = (const int*)d_in[0];
    const float* offset = (const float*)d_in[1];
    const float* scale  = (const float*)d_in[2];
    float*       out    = (float*)d_out;

    prefix_kernel<<<N8 / 256, 256>>>(flags);
    leaf_kernel<<<N9 / 256, 256>>>(flags, offset, scale, out);
}

// round 3
// speedup vs baseline: 1.1065x; 1.1065x over previous
#include <cuda_runtime.h>

// NbitTreeDecoder, single fused kernel.
// Key identities: X = (prefix27 << 3) | j;  Xr = brev32(X) >> 2
//   = (brev32(prefix27) >> 5) | (rev3(j) << 27)
// so fields x (bits 0-9) and y (bits 10-19) are shared by all 4 leaves of a
// level-9 node; only z (bits 20-29) depends on j.
// float(field) = asfloat(0x4B000000 | field) - 2^23   (exact, replaces I2F)

struct Lut { unsigned v[256]; };

__host__ __device__ constexpr Lut make_lut() {
    Lut l{};
    for (int f = 0; f < 256; f++) {
        unsigned jp = 0u, rp = 0u; int cnt = 0;
        for (int b = 0; b < 8 && cnt < 4; b++) {
            if (f & (1 << b)) {
                unsigned r3 = (unsigned)(((b & 1) << 2) | (b & 2) | ((b >> 2) & 1));
                jp |= (unsigned)b << (4 * cnt);
                rp |= r3 << (4 * cnt);
                cnt++;
            }
        }
        l.v[f] = jp | (rp << 16);   // low16: set-bit positions, high16: rev3 of them
    }
    return l;
}

__device__ constexpr Lut g_lut = make_lut();

#define MAGIC  0x4B000000u
#define MAGICF 8388608.0f

__global__ void __launch_bounds__(256)
decode_kernel(const int* __restrict__ flags,
              const float* __restrict__ offset,
              const float* __restrict__ scale,
              float* __restrict__ out)
{
    __shared__ unsigned slut[256];
    __shared__ unsigned sp[256];   // 27-bit prefix per level-9 node of this block
    const unsigned tid = threadIdx.x;
    const unsigned blk = blockIdx.x;

    slut[tid] = g_lut.v[tid];
    __syncthreads();

    // Phase A: threads 0..63 each resolve one level-8 node (levels 0..7 walk,
    // then expand the level-8 flag into 4 child prefixes).
    if (tid < 64) {
        const unsigned n8 = blk * 64u + tid;
        const unsigned OFF[8] = {0u, 1u, 5u, 21u, 85u, 341u, 1365u, 5461u};
        unsigned prefix = 0u;
#pragma unroll
        for (int t = 0; t < 8; t++) {
            const unsigned sh   = (unsigned)(14 - 2 * t);
            const unsigned nt   = n8 >> sh >> 2;               // ancestor at level t
            const unsigned flag = (unsigned)__ldg(flags + OFF[t] + nt);
            const unsigned d    = (n8 >> sh) & 3u;             // branch digit
            prefix = (prefix << 3) | ((slut[flag] >> (4u * d)) & 7u);
        }
        const unsigned f8 = (unsigned)__ldg(flags + 21845u + n8);
        const unsigned jp = slut[f8];                          // packed positions
        const unsigned p3 = prefix << 3;
        sp[4u * tid + 0u] = p3 | (jp & 7u);
        sp[4u * tid + 1u] = p3 | ((jp >> 4) & 7u);
        sp[4u * tid + 2u] = p3 | ((jp >> 8) & 7u);
        sp[4u * tid + 3u] = p3 | ((jp >> 12) & 7u);
    }
    __syncthreads();

    // Phase B: one thread per level-9 node -> 4 leaves (48B contiguous).
    const unsigned n9 = blk * 256u + tid;
    const unsigned p  = sp[tid];
    const unsigned f9 = (unsigned)__ldg(flags + 87381u + n9);
    const unsigned rp = slut[f9] >> 16;                        // packed rev3(j)

    const float s0 = __ldg(scale),     s1 = __ldg(scale + 1),  s2 = __ldg(scale + 2);
    const float o0 = __ldg(offset),    o1 = __ldg(offset + 1), o2 = __ldg(offset + 2);

    const unsigned B = __brev(p) >> 5;                         // reversed prefix, bits 0..26

    const float x = fmaf(__uint_as_float(MAGIC | (B & 1023u)) - MAGICF, s0, o0);
    const float y = fmaf(__uint_as_float(MAGIC | ((B >> 10) & 1023u)) - MAGICF, s1, o1);

    const unsigned M2  = MAGIC | (B >> 20);                    // low 7 bits of z-field
    const unsigned tsh = rp << 7;                              // rev3(j_d) at bits 4d+7..4d+9
    float z[4];
#pragma unroll
    for (int d = 0; d < 4; d++) {
        const unsigned f2 = ((tsh >> (4 * d)) & 0x380u) | M2;
        z[d] = fmaf(__uint_as_float(f2) - MAGICF, s2, o2);
    }

    float4* outv = reinterpret_cast<float4*>(out + (size_t)n9 * 12u);
    outv[0] = make_float4(x,    y,    z[0], x);
    outv[1] = make_float4(y,    z[1], x,    y);
    outv[2] = make_float4(z[2], x,    y,    z[3]);
}

extern "C" void kernel_launch(void* const* d_in, const int* in_sizes, int n_in,
                              void* d_out, int out_size) {
    const int*   flags  = (const int*)d_in[0];
    const float* offset = (const float*)d_in[1];
    const float* scale  = (const float*)d_in[2];
    float*       out    = (float*)d_out;

    decode_kernel<<<1024, 256>>>(flags, offset, scale, out);
}